// round 16
// baseline (speedup 1.0000x reference)
#include <cuda_runtime.h>
#include <cstdint>

#define BGRAPHS   16
#define NPG       2048
#define KNN       16
#define MIN_DISTR 5
#define CPB       32                 // centers per block
#define PARTS     8                  // threads per center
#define CANDS     (NPG / PARTS)      // 256 candidates per part
#define THREADS   (CPB * PARTS)      // 256 threads per block
#define CAP       128                // pass-2 collection capacity per center
#define TMARGIN   0.01f              // covers |d2 - (t + csq)| rounding (<=~6e-4)

// monotone float -> uint key (total order matching float <)
__device__ __forceinline__ unsigned sortkey(float f)
{
    unsigned u = __float_as_uint(f);
    return u ^ (unsigned)(((int)u >> 31) | 0x80000000);
}

// exact reference-rounded squared distance (validated rounds 3-15) — selection only
__device__ __forceinline__ float d2_ref(float cx, float cy, float cz, float csq,
                                        const float4 v)
{
    float dot = __fmaf_rn(cz, v.z, __fmaf_rn(cy, v.y, __fmul_rn(cx, v.x)));
    return __fmaf_rn(-2.0f, dot, __fadd_rn(csq, v.w));
}

// cheap surrogate: t = fma(-2, dot, w); order == order(d2) shifted by csq
// up to <=~6e-4 discrepancy (absorbed by TMARGIN).
__device__ __forceinline__ float t_surr(float cx, float cy, float cz,
                                        const float4 v)
{
    float dot = __fmaf_rn(cz, v.z, __fmaf_rn(cy, v.y, __fmul_rn(cx, v.x)));
    return __fmaf_rn(-2.0f, dot, v.w);
}

__global__ __launch_bounds__(THREADS, 5)
void knn_kernel(const float* __restrict__ pos, float2* __restrict__ out)
{
    __shared__ float4         sh[NPG];                 // 32768 B: x,y,z,|p|^2
    __shared__ float          pvals[CPB * PARTS * 3];  //  3072 B: per-part 3 smallest t
    __shared__ float          bnd[CPB];                //   128 B
    __shared__ int            cnt[CPB];                //   128 B
    __shared__ unsigned short jbuf[CPB * CAP];         //  8192 B

    const int tid = threadIdx.x;
    const int p   = tid >> 5;        // part 0..7 (uniform per warp)
    const int c   = tid & 31;        // center-in-block (lane)

    const int g  = blockIdx.x >> 6;           // 64 blocks per graph
    const int cb = (blockIdx.x & 63) * CPB;   // center base (local)
    const int gb = g * NPG;

    if (tid < CPB) cnt[tid] = 0;

    // ---- load graph into smem: {x,y,z,|p|^2} (sq per reference rounding) ----
    for (int i = tid; i < NPG; i += THREADS) {
        const float* q = pos + 3ull * (unsigned long long)(gb + i);
        float x = q[0], y = q[1], z = q[2];
        float sq = __fadd_rn(__fadd_rn(__fmul_rn(x, x), __fmul_rn(y, y)),
                             __fmul_rn(z, z));
        sh[i] = make_float4(x, y, z, sq);
    }
    __syncthreads();

    const int    lc = cb + c;
    const float4 cc = sh[lc];
    const float  cx = cc.x, cy = cc.y, cz = cc.z;
    const float  INF = __int_as_float(0x7f800000);

    // ---- pass 1: 3 smallest t over a stride-2 HALF substream, branchless ----
    // Subset only loosens the bound (still a valid upper bound). No self-check
    // (self tolerated by the 17th-smallest bound below). Rank model: kept
    // sample ranks ~8/16/24 per part => B at global rank ~50-70 => m << CAP.
    float h0 = INF, h1 = INF, h2 = INF;
    const int jb = p * CANDS;
#pragma unroll 8
    for (int j = jb; j < jb + CANDS; j += 2) {
        float t = t_surr(cx, cy, cz, sh[j]);
        float t0 = fminf(h0, t),  x1 = fmaxf(h0, t);  h0 = t0;
        float t1 = fminf(h1, x1), x2 = fmaxf(h1, x1); h1 = t1;
        h2 = fminf(h2, x2);
    }
    {
        float* pv = pvals + (c * PARTS + p) * 3;
        pv[0] = h0; pv[1] = h1; pv[2] = h2;
    }
    __syncthreads();

    // ---- bound: 17th smallest of the 24 kept t (= 8th largest) + margin ----
    // >=17 distinct elements with t <= B; at most one is self => >=16 non-self
    // => B >= true 16th-smallest non-self t; TMARGIN covers t<->d2 rounding.
    if (tid < CPB) {
        float g8[8];
#pragma unroll
        for (int t = 0; t < 8; ++t) g8[t] = -INF;
        const float* pv = pvals + tid * PARTS * 3;
        for (int e = 0; e < PARTS * 3; ++e) {
            float x = pv[e];
#pragma unroll
            for (int t = 0; t < 8; ++t) {
                float hi = fmaxf(g8[t], x);
                x = fminf(g8[t], x);
                g8[t] = hi;
            }
        }
        bnd[tid] = g8[7] + TMARGIN;
    }
    __syncthreads();

    // ---- pass 2: full substream, collect t <= B (self included) ----
    const float B = bnd[c];
#pragma unroll 4
    for (int j = jb; j < jb + CANDS; ++j) {
        float t = t_surr(cx, cy, cz, sh[j]);
        if (t <= B) {
            int s = atomicAdd(&cnt[c], 1);
            if (s < CAP) jbuf[c * CAP + s] = (unsigned short)j;
        }
    }
    __syncthreads();

    // ---- selection (exact d2) + filters + emit: one lane per center ----
    if (tid < CPB) {
        const int    lc2 = cb + tid;
        const float4 c0  = sh[lc2];
        const float  ax = c0.x, ay = c0.y, az = c0.z, asq = c0.w;

        unsigned long long hd[KNN];
#pragma unroll
        for (int t = 0; t < KNN; ++t) hd[t] = ~0ull;

        const int m = cnt[tid];
        if (m <= CAP) {
            for (int e = 0; e < m; ++e) {
                const int j = jbuf[tid * CAP + e];
                if (j == lc2) continue;          // skip self (collected above)
                float d2 = d2_ref(ax, ay, az, asq, sh[j]);
                unsigned long long key =
                    ((unsigned long long)sortkey(d2) << 32) | (unsigned)j;
                if (key < hd[KNN - 1]) {
#pragma unroll
                    for (int t = 0; t < KNN; ++t) {
                        unsigned long long lo = key < hd[t] ? key : hd[t];
                        unsigned long long hi = key < hd[t] ? hd[t] : key;
                        hd[t] = lo; key = hi;
                    }
                }
            }
        } else {
            // overflow fallback: exact full scan (rare by rank model; cost
            // contained to the overflowing lane)
            for (int j = 0; j < NPG; ++j) {
                if (j == lc2) continue;
                float d2 = d2_ref(ax, ay, az, asq, sh[j]);
                unsigned long long key =
                    ((unsigned long long)sortkey(d2) << 32) | (unsigned)j;
                if (key < hd[KNN - 1]) {
#pragma unroll
                    for (int t = 0; t < KNN; ++t) {
                        unsigned long long lo = key < hd[t] ? key : hd[t];
                        unsigned long long hi = key < hd[t] ? hd[t] : key;
                        hd[t] = lo; key = hi;
                    }
                }
            }
        }

        const int ctr = gb + lc2;
#pragma unroll
        for (int k = 0; k < KNN; ++k) {
            float2 e = make_float2(-1.0f, -1.0f);
            if (hd[k] != ~0ull) {
                const int nl  = (int)(unsigned)(hd[k] & 0xFFFFFFFFull);
                const int nbr = gb + nl;
                const float4 v = sh[nl];
                // degenerate-edge filter, reference formula
                float dx = __fadd_rn(v.x, -ax);
                float dy = __fadd_rn(v.y, -ay);
                float dz = __fadd_rn(v.z, -az);
                float dn2 = __fadd_rn(__fadd_rn(__fmul_rn(dx, dx),
                                                __fmul_rn(dy, dy)),
                                      __fmul_rn(dz, dz));
                int  rd    = nbr > ctr ? (nbr - ctr) : (ctr - nbr);
                bool valid = (rd >= MIN_DISTR) && (sqrtf(dn2) >= 1e-10f);
                if (valid) e = make_float2((float)nbr, (float)ctr);
            }
            out[ctr * KNN + k] = e;
        }
    }
}

extern "C" void kernel_launch(void* const* d_in, const int* in_sizes, int n_in,
                              void* d_out, int out_size)
{
    const float* pos = (const float*)d_in[0];
    for (int i = 0; i < n_in; ++i)
        if (in_sizes[i] == BGRAPHS * NPG * 3) { pos = (const float*)d_in[i]; break; }
    float2* out = (float2*)d_out;

    dim3 grid(BGRAPHS * (NPG / CPB));   // 1024 blocks
    dim3 block(THREADS);                // 256 threads
    knn_kernel<<<grid, block>>>(pos, out);
}

// round 17
// speedup vs baseline: 1.1456x; 1.1456x over previous
#include <cuda_runtime.h>
#include <cstdint>

#define BGRAPHS   16
#define NPG       2048
#define KNN       16
#define MIN_DISTR 5
#define CPB       64                 // centers per block (2 per thread)
#define PARTS     8                  // parts per center
#define CANDS     (NPG / PARTS)      // 256 candidates per part
#define THREADS   256                // (CPB/2) * PARTS
#define CAP       64                 // pass-2 collection capacity per center
#define TMARGIN   0.01f              // covers |d2 - (t + csq)| rounding (<=~6e-4)

// monotone float -> uint key (total order matching float <)
__device__ __forceinline__ unsigned sortkey(float f)
{
    unsigned u = __float_as_uint(f);
    return u ^ (unsigned)(((int)u >> 31) | 0x80000000);
}

// exact reference-rounded squared distance (validated rounds 3-16) — selection only
__device__ __forceinline__ float d2_ref(float cx, float cy, float cz, float csq,
                                        const float4 v)
{
    float dot = __fmaf_rn(cz, v.z, __fmaf_rn(cy, v.y, __fmul_rn(cx, v.x)));
    return __fmaf_rn(-2.0f, dot, __fadd_rn(csq, v.w));
}

// cheap surrogate: t = fma(-2, dot, w); order == order(d2) shifted by csq
// up to <=~6e-4 discrepancy (absorbed by TMARGIN). (validated round 15)
__device__ __forceinline__ float t_surr(float cx, float cy, float cz,
                                        const float4 v)
{
    float dot = __fmaf_rn(cz, v.z, __fmaf_rn(cy, v.y, __fmul_rn(cx, v.x)));
    return __fmaf_rn(-2.0f, dot, v.w);
}

__global__ __launch_bounds__(THREADS, 4)
void knn_kernel(const float* __restrict__ pos, float2* __restrict__ out)
{
    __shared__ float4         sh[NPG];                 // 32768 B: x,y,z,|p|^2
    __shared__ float          pvals[CPB * PARTS * 3];  //  6144 B: per-part 3 smallest t
    __shared__ float          bnd[CPB];                //   256 B
    __shared__ int            cnt[CPB];                //   256 B
    __shared__ unsigned short jbuf[CPB * CAP];         //  8192 B  (total ~46.5 KB)

    const int tid = threadIdx.x;
    const int p   = tid >> 5;        // part 0..7 (uniform per warp)
    const int c   = tid & 31;        // first center (lane); second is c+32

    const int g  = blockIdx.x >> 5;           // 32 blocks per graph
    const int cb = (blockIdx.x & 31) * CPB;   // center base (local)
    const int gb = g * NPG;

    if (tid < CPB) cnt[tid] = 0;

    // ---- load graph into smem: {x,y,z,|p|^2} (sq per reference rounding) ----
    for (int i = tid; i < NPG; i += THREADS) {
        const float* q = pos + 3ull * (unsigned long long)(gb + i);
        float x = q[0], y = q[1], z = q[2];
        float sq = __fadd_rn(__fadd_rn(__fmul_rn(x, x), __fmul_rn(y, y)),
                             __fmul_rn(z, z));
        sh[i] = make_float4(x, y, z, sq);
    }
    __syncthreads();

    const int lcA = cb + c;            // center A
    const int lcB = cb + c + 32;       // center B
    const float4 cA = sh[lcA];
    const float4 cB = sh[lcB];
    const float INF = __int_as_float(0x7f800000);

    // ---- pass 1: FULL substream; 3 smallest t for TWO centers per load ----
    // No self-checks (tolerated by 17th-smallest bound). Two independent
    // chains per thread double the FMNMX dependency spacing (free ILP).
    float a0 = INF, a1 = INF, a2 = INF;   // center A chain
    float b0 = INF, b1 = INF, b2 = INF;   // center B chain
    const int jb = p * CANDS;
#pragma unroll 4
    for (int j = jb; j < jb + CANDS; ++j) {
        const float4 v = sh[j];                       // ONE load, two t
        float tA = t_surr(cA.x, cA.y, cA.z, v);
        float tB = t_surr(cB.x, cB.y, cB.z, v);
        float t0 = fminf(a0, tA), x1 = fmaxf(a0, tA); a0 = t0;
        float t1 = fminf(a1, x1), x2 = fmaxf(a1, x1); a1 = t1;
        a2 = fminf(a2, x2);
        float s0 = fminf(b0, tB), y1 = fmaxf(b0, tB); b0 = s0;
        float s1 = fminf(b1, y1), y2 = fmaxf(b1, y1); b1 = s1;
        b2 = fminf(b2, y2);
    }
    {
        float* pvA = pvals + (c * PARTS + p) * 3;
        pvA[0] = a0; pvA[1] = a1; pvA[2] = a2;
        float* pvB = pvals + ((c + 32) * PARTS + p) * 3;
        pvB[0] = b0; pvB[1] = b1; pvB[2] = b2;
    }
    __syncthreads();

    // ---- bound: 17th smallest of the 24 kept t (= 8th largest) + margin ----
    // >=17 distinct elements with t <= B; at most one is self => >=16 non-self
    // => valid upper bound on true 16th; TMARGIN covers t<->d2 rounding.
    if (tid < CPB) {
        float g8[8];
#pragma unroll
        for (int t = 0; t < 8; ++t) g8[t] = -INF;
        const float* pv = pvals + tid * PARTS * 3;
        for (int e = 0; e < PARTS * 3; ++e) {
            float x = pv[e];
#pragma unroll
            for (int t = 0; t < 8; ++t) {
                float hi = fmaxf(g8[t], x);
                x = fminf(g8[t], x);
                g8[t] = hi;
            }
        }
        bnd[tid] = g8[7] + TMARGIN;
    }
    __syncthreads();

    // ---- pass 2: one load, two bound tests (self included, skipped later) ----
    const float BA = bnd[c];
    const float BB = bnd[c + 32];
#pragma unroll 4
    for (int j = jb; j < jb + CANDS; ++j) {
        const float4 v = sh[j];
        float tA = t_surr(cA.x, cA.y, cA.z, v);
        float tB = t_surr(cB.x, cB.y, cB.z, v);
        if (tA <= BA) {
            int s = atomicAdd(&cnt[c], 1);
            if (s < CAP) jbuf[c * CAP + s] = (unsigned short)j;
        }
        if (tB <= BB) {
            int s = atomicAdd(&cnt[c + 32], 1);
            if (s < CAP) jbuf[(c + 32) * CAP + s] = (unsigned short)j;
        }
    }
    __syncthreads();

    // ---- selection (exact d2) + filters + emit: one lane per center (2 warps) ----
    if (tid < CPB) {
        const int    lc2 = cb + tid;
        const float4 c0  = sh[lc2];
        const float  ax = c0.x, ay = c0.y, az = c0.z, asq = c0.w;

        unsigned long long hd[KNN];
#pragma unroll
        for (int t = 0; t < KNN; ++t) hd[t] = ~0ull;

        const int m = cnt[tid];
        if (m <= CAP) {
            for (int e = 0; e < m; ++e) {
                const int j = jbuf[tid * CAP + e];
                if (j == lc2) continue;          // skip self (collected above)
                float d2 = d2_ref(ax, ay, az, asq, sh[j]);
                unsigned long long key =
                    ((unsigned long long)sortkey(d2) << 32) | (unsigned)j;
                if (key < hd[KNN - 1]) {
#pragma unroll
                    for (int t = 0; t < KNN; ++t) {
                        unsigned long long lo = key < hd[t] ? key : hd[t];
                        unsigned long long hi = key < hd[t] ? hd[t] : key;
                        hd[t] = lo; key = hi;
                    }
                }
            }
        } else {
            // overflow fallback: exact full scan (rare; contained per lane)
            for (int j = 0; j < NPG; ++j) {
                if (j == lc2) continue;
                float d2 = d2_ref(ax, ay, az, asq, sh[j]);
                unsigned long long key =
                    ((unsigned long long)sortkey(d2) << 32) | (unsigned)j;
                if (key < hd[KNN - 1]) {
#pragma unroll
                    for (int t = 0; t < KNN; ++t) {
                        unsigned long long lo = key < hd[t] ? key : hd[t];
                        unsigned long long hi = key < hd[t] ? hd[t] : key;
                        hd[t] = lo; key = hi;
                    }
                }
            }
        }

        const int ctr = gb + lc2;
#pragma unroll
        for (int k = 0; k < KNN; ++k) {
            float2 e = make_float2(-1.0f, -1.0f);
            if (hd[k] != ~0ull) {
                const int nl  = (int)(unsigned)(hd[k] & 0xFFFFFFFFull);
                const int nbr = gb + nl;
                const float4 v = sh[nl];
                // degenerate-edge filter, reference formula
                float dx = __fadd_rn(v.x, -ax);
                float dy = __fadd_rn(v.y, -ay);
                float dz = __fadd_rn(v.z, -az);
                float dn2 = __fadd_rn(__fadd_rn(__fmul_rn(dx, dx),
                                                __fmul_rn(dy, dy)),
                                      __fmul_rn(dz, dz));
                int  rd    = nbr > ctr ? (nbr - ctr) : (ctr - nbr);
                bool valid = (rd >= MIN_DISTR) && (sqrtf(dn2) >= 1e-10f);
                if (valid) e = make_float2((float)nbr, (float)ctr);
            }
            out[ctr * KNN + k] = e;
        }
    }
}

extern "C" void kernel_launch(void* const* d_in, const int* in_sizes, int n_in,
                              void* d_out, int out_size)
{
    const float* pos = (const float*)d_in[0];
    for (int i = 0; i < n_in; ++i)
        if (in_sizes[i] == BGRAPHS * NPG * 3) { pos = (const float*)d_in[i]; break; }
    float2* out = (float2*)d_out;

    dim3 grid(BGRAPHS * (NPG / CPB));   // 512 blocks: single wave at 4/SM
    dim3 block(THREADS);                // 256 threads
    knn_kernel<<<grid, block>>>(pos, out);
}